// round 16
// baseline (speedup 1.0000x reference)
#include <cuda_runtime.h>
#include <cuda_fp16.h>
#include <math.h>
#include <stdint.h>

#define BN 4096
#define DN 512
#define CN 3
#define NT 32                       // 4096/128 tiles per dim
#define NBLK (NT * (NT + 1) / 2)    // 528 upper-tri tile pairs
#define NDC 4                       // double-chunks of K=128
#define STAGE_BYTES 65536           // A(2x16K) + B(2x16K)
#define NSTAGE 3
#define DSMEM_BYTES (NSTAGE * STAGE_BYTES)
#define NRW 128                     // row-scalar warps (32 rows each)
#define GT 512                      // threads
#define NPERS 148                   // persistent CTAs

// ---------------- device scratch ----------------
__device__ __align__(16) __half g_hi[BN * DN];
__device__ unsigned int g_posd2[BN];
__device__ unsigned int g_negd2[BN];
__device__ double       g_acc[4];            // 0 pos 1 neg 2 semi 3 q
__device__ double       g_rows_part[NRW][5];
__device__ int          g_cnt_part[NRW][CN];
__device__ int          g_done;
__device__ int          g_work;

// ---------------- PTX helpers (base sm_103-legal only) ----------------
__device__ __forceinline__ uint32_t smem_u32(const void* p) {
    uint32_t a;
    asm("{ .reg .u64 t; cvta.to.shared.u64 t, %1; cvt.u32.u64 %0, t; }" : "=r"(a) : "l"(p));
    return a;
}
#define SW128(x) ((x) ^ (((x) >> 3) & 0x70))

__device__ __forceinline__ void cp16(uint32_t smem, const void* g) {
    asm volatile("cp.async.cg.shared.global [%0], [%1], 16;" :: "r"(smem), "l"(g));
}
#define CP_COMMIT()  asm volatile("cp.async.commit_group;" ::: "memory")
#define CP_WAIT(n)   asm volatile("cp.async.wait_group %0;" :: "n"(n) : "memory")

__device__ __forceinline__ void ldsm_x4(uint32_t& r0, uint32_t& r1, uint32_t& r2, uint32_t& r3,
                                        uint32_t addr) {
    asm volatile("ldmatrix.sync.aligned.m8n8.x4.shared.b16 {%0,%1,%2,%3}, [%4];"
                 : "=r"(r0), "=r"(r1), "=r"(r2), "=r"(r3) : "r"(addr));
}

__device__ __forceinline__ void mma_f16(float* c, const uint32_t* a, const uint32_t* b) {
    asm volatile("mma.sync.aligned.m16n8k16.row.col.f32.f16.f16.f32 "
                 "{%0,%1,%2,%3}, {%4,%5,%6,%7}, {%8,%9}, {%0,%1,%2,%3};"
                 : "+f"(c[0]), "+f"(c[1]), "+f"(c[2]), "+f"(c[3])
                 : "r"(a[0]), "r"(a[1]), "r"(a[2]), "r"(a[3]), "r"(b[0]), "r"(b[1]));
}

// ---------------- misc helpers ----------------
__device__ __forceinline__ float digamma_f(float x) {
    float r = 0.0f;
    while (x < 6.0f) { r -= 1.0f / x; x += 1.0f; }
    float f = 1.0f / (x * x);
    return logf(x) - 0.5f / x
        - f * (1.0f/12.0f - f * (1.0f/120.0f - f * (1.0f/252.0f - f * (1.0f/240.0f))))
        + r;
}

__device__ __forceinline__ void decode_tile(int t, int& bi, int& bj) {
    float ff = (65.0f - sqrtf(4225.0f - 8.0f * (float)t)) * 0.5f;
    int b = (int)ff;
    if (b < 0) b = 0;
    while (b * NT - (b * (b - 1)) / 2 > t) b--;
    while ((b + 1) * NT - ((b + 1) * b) / 2 <= t) b++;
    bi = b;
    bj = b + (t - (b * NT - (b * (b - 1)) / 2));
}

// ---------------- prep kernel ----------------
__global__ void __launch_bounds__(GT) k_prep(const float* __restrict__ f, const float* __restrict__ logits,
                       const int* __restrict__ targets, const float* __restrict__ alpha,
                       const float* __restrict__ fa, const float* __restrict__ cw) {
    int tid = threadIdx.x;
    int gid = blockIdx.x * GT + tid;
    int lane = tid & 31;
    int gw = gid >> 5;
    const int TW = NPERS * GT / 32;

    for (int row = gw; row < BN; row += TW) {
        const float4* fr = (const float4*)(f + (size_t)row * DN);
        float4 v[4];
        float ss = 0.0f;
        #pragma unroll
        for (int i = 0; i < 4; i++) {
            v[i] = fr[lane + 32 * i];
            ss += v[i].x*v[i].x + v[i].y*v[i].y + v[i].z*v[i].z + v[i].w*v[i].w;
        }
        for (int o = 16; o; o >>= 1) ss += __shfl_xor_sync(0xffffffffu, ss, o);
        float inv = 1.0f / fmaxf(sqrtf(ss), 1e-12f);
        uint2* out = (uint2*)g_hi + (size_t)row * 128;
        #pragma unroll
        for (int i = 0; i < 4; i++) {
            __half h0 = __float2half_rn(v[i].x * inv), h1 = __float2half_rn(v[i].y * inv);
            __half h2 = __float2half_rn(v[i].z * inv), h3 = __float2half_rn(v[i].w * inv);
            uint2 hv;
            hv.x = (uint32_t)__half_as_ushort(h0) | ((uint32_t)__half_as_ushort(h1) << 16);
            hv.y = (uint32_t)__half_as_ushort(h2) | ((uint32_t)__half_as_ushort(h3) << 16);
            out[lane + 32 * i] = hv;
        }
    }

    if (gid < BN) { g_posd2[gid] = 0u; g_negd2[gid] = 0x7F7FFFFFu; }
    if (gid < 4) g_acc[gid] = 0.0;
    if (gid == 4) g_done = 0;
    if (gid == 5) g_work = 0;

    if (gw < NRW) {
        int i = gw * 32 + lane;
        int t = targets[i];

        float l0 = logits[3*i], l1 = logits[3*i+1], l2 = logits[3*i+2];
        float m  = fmaxf(l0, fmaxf(l1, l2));
        float e0 = expf(l0-m), e1 = expf(l1-m), e2 = expf(l2-m);
        float Z  = e0 + e1 + e2;
        float lse = m + logf(Z);
        float lp0 = l0-lse, lp1 = l1-lse, lp2 = l2-lse;
        float lpt = (t == 0) ? lp0 : (t == 1) ? lp1 : lp2;
        float nll = -lpt;
        float ce_ls = 0.9f * nll - 0.1f * ((lp0+lp1+lp2) * (1.0f/3.0f));
        float pt = expf(-ce_ls);
        float om = 1.0f - pt;
        float fterm = fa[t] * om * om * ce_ls;
        float wnll  = cw[t] * nll;
        float p0 = e0/Z, p1 = e1/Z, p2 = e2/Z;
        float bterm = (t == 0) ? (p1 + 0.6f*p2)
                    : (t == 2) ? (p1 + 0.4f*p0)
                    :            4.5f * (1.0f - p1 + 0.3f*(p0 + p2));

        float a0 = alpha[3*i], a1 = alpha[3*i+1], a2 = alpha[3*i+2];
        float S  = a0 + a1 + a2 + 1e-8f;
        float at = (t == 0) ? a0 : (t == 1) ? a1 : a2;
        float lik = digamma_f(S) - digamma_f(at + 1e-8f);
        float b0 = (t == 0) ? 1.0f : a0;
        float b1 = (t == 1) ? 1.0f : a1;
        float b2 = (t == 2) ? 1.0f : a2;
        float ats = b0 + b1 + b2 + 1e-8f;
        float dga = digamma_f(ats + 1e-8f);
        float kl = lgammaf(ats) - (lgammaf(b0+1e-8f) + lgammaf(b1+1e-8f) + lgammaf(b2+1e-8f))
                 + (b0-1.0f) * (digamma_f(b0+1e-8f) - dga)
                 + (b1-1.0f) * (digamma_f(b1+1e-8f) - dga)
                 + (b2-1.0f) * (digamma_f(b2+1e-8f) - dga);

        double vals[5] = { (double)fterm, (double)wnll, (double)bterm, (double)lik, (double)kl };
        #pragma unroll
        for (int r = 0; r < 5; r++) {
            double v = vals[r];
            for (int o = 16; o; o >>= 1) v += __shfl_xor_sync(0xffffffffu, v, o);
            if (lane == 0) g_rows_part[gw][r] = v;
        }
        #pragma unroll
        for (int r = 0; r < CN; r++) {
            int v = (t == r) ? 1 : 0;
            for (int o = 16; o; o >>= 1) v += __shfl_xor_sync(0xffffffffu, v, o);
            if (lane == 0) g_cnt_part[gw][r] = v;
        }
    }
}

// gmem -> smem double-chunk loader: old chunks 2*c2, 2*c2+1; layout A0,A1,B0,B1 (16KB each)
__device__ __forceinline__ void load_chunk2(uint32_t sb, int i0, int j0, int c2, int tid) {
    const uint4* gh4 = (const uint4*)g_hi;
    #pragma unroll
    for (int half = 0; half < 2; half++) {
        int c = 2 * c2 + half;
        #pragma unroll
        for (int p = 0; p < 2; p++) {
            int lin = p * GT + tid;
            int r = lin >> 3, q = lin & 7;
            uint32_t so = SW128((uint32_t)(r * 128 + q * 16));
            cp16(sb + half * 16384 +         so, gh4 + (size_t)(i0 + r) * 64 + c * 8 + q);
            cp16(sb + half * 16384 + 32768 + so, gh4 + (size_t)(j0 + r) * 64 + c * 8 + q);
        }
    }
}

// persistent HMMA Gram kernel, rolling 3-stage pipeline, fragment double-buffering
__global__ void __launch_bounds__(GT, 1) k_gram(const int* __restrict__ targets,
                                                const float* __restrict__ cw,
                                                const int* __restrict__ epoch_p,
                                                float* __restrict__ out) {
    extern __shared__ __align__(1024) char dsm_raw[];
    __shared__ int sti[2][128], stj[2][128];
    __shared__ unsigned int srp[2][128], srn[2][128], scp[2][128], scn[2][128];
    __shared__ double sredd[16];
    __shared__ int s_cur, s_next;

    int tid = threadIdx.x;
    int w = tid >> 5, lane = tid & 31;
    int wm = w >> 2, wn = w & 3;
    uint32_t dsm = smem_u32(dsm_raw);

    int a_row = wm * 32 + (lane & 15);
    int a_colb = (lane >> 4) * 8;
    int b_row = wn * 32 + (lane & 7) + ((lane >> 4) << 3);
    int b_colb = ((lane >> 3) & 1) * 8;
    int r_lo = lane >> 2;
    int c_lo = (lane & 3) * 2;

    float posA = 0.f, negA = 0.f, semA = 0.f, qA = 0.f;

    if (tid == 0) s_cur = atomicAdd(&g_work, 1);
    __syncthreads();
    int tile = s_cur;
    int bi, bj;
    decode_tile(tile, bi, bj);
    int i0 = bi * 128, j0 = bj * 128;
    int p = 0;
    if (tid < 128) {
        sti[0][tid] = targets[i0 + tid];
        stj[0][tid] = targets[j0 + tid];
        srp[0][tid] = 0u; srn[0][tid] = 0x7F7FFFFFu;
        scp[0][tid] = 0u; scn[0][tid] = 0x7F7FFFFFu;
    }
    int sb0 = 0;
    load_chunk2(dsm + (uint32_t)sb0 * STAGE_BYTES,                  i0, j0, 0, tid); CP_COMMIT();
    load_chunk2(dsm + (uint32_t)((sb0 + 1) % NSTAGE) * STAGE_BYTES, i0, j0, 1, tid); CP_COMMIT();

    for (;;) {
        bool diag = (bi == bj);
        int i0n = 0, j0n = 0, nt = NBLK;

        float acc[2][4][4];
        #pragma unroll
        for (int am = 0; am < 2; am++)
            #pragma unroll
            for (int bn = 0; bn < 4; bn++)
                #pragma unroll
                for (int e = 0; e < 4; e++) acc[am][bn][e] = 0.0f;

        #pragma unroll
        for (int iter = 0; iter < NDC; iter++) {
            CP_WAIT(1);
            __syncthreads();
            if (iter == 0 && tid == 0) s_next = atomicAdd(&g_work, 1);
            if (iter == 1) {
                nt = s_next;
                if (nt < NBLK) {
                    int bin, bjn;
                    decode_tile(nt, bin, bjn);
                    i0n = bin * 128; j0n = bjn * 128;
                }
                if (tid < 128) {
                    if (nt < NBLK) {
                        sti[p ^ 1][tid] = targets[i0n + tid];
                        stj[p ^ 1][tid] = targets[j0n + tid];
                    }
                    srp[p ^ 1][tid] = 0u; srn[p ^ 1][tid] = 0x7F7FFFFFu;
                    scp[p ^ 1][tid] = 0u; scn[p ^ 1][tid] = 0x7F7FFFFFu;
                }
            }

            uint32_t sb = dsm + (uint32_t)((sb0 + iter) % NSTAGE) * STAGE_BYTES;

            // ---- 8 sub-ksteps with explicit fragment double-buffering ----
            uint32_t ah2[2][2][4], bh2[2][4][2];
            // load fragments for step 0 into buffer 0
            {
                uint32_t sba = sb, sbb = sb + 32768;
                #pragma unroll
                for (int am = 0; am < 2; am++) {
                    uint32_t off = SW128((uint32_t)((a_row + am * 16) * 128 + a_colb * 2));
                    ldsm_x4(ah2[0][am][0], ah2[0][am][1], ah2[0][am][2], ah2[0][am][3], sba + off);
                }
                #pragma unroll
                for (int bp = 0; bp < 2; bp++) {
                    uint32_t off = SW128((uint32_t)((b_row + bp * 16) * 128 + b_colb * 2));
                    ldsm_x4(bh2[0][bp*2][0], bh2[0][bp*2][1], bh2[0][bp*2+1][0], bh2[0][bp*2+1][1], sbb + off);
                }
            }
            #pragma unroll
            for (int s = 0; s < 8; s++) {
                int buf = s & 1;
                if (s < 7) {
                    int sn = s + 1;
                    int kbn = sn >> 2, ksn = sn & 3;
                    uint32_t sba = sb + kbn * 16384;
                    uint32_t sbb = sb + 32768 + kbn * 16384;
                    int k0n = ksn * 16;
                    int nb = buf ^ 1;
                    #pragma unroll
                    for (int am = 0; am < 2; am++) {
                        uint32_t off = SW128((uint32_t)((a_row + am * 16) * 128 + (k0n + a_colb) * 2));
                        ldsm_x4(ah2[nb][am][0], ah2[nb][am][1], ah2[nb][am][2], ah2[nb][am][3], sba + off);
                    }
                    #pragma unroll
                    for (int bp = 0; bp < 2; bp++) {
                        uint32_t off = SW128((uint32_t)((b_row + bp * 16) * 128 + (k0n + b_colb) * 2));
                        ldsm_x4(bh2[nb][bp*2][0], bh2[nb][bp*2][1], bh2[nb][bp*2+1][0], bh2[nb][bp*2+1][1], sbb + off);
                    }
                }
                #pragma unroll
                for (int am = 0; am < 2; am++)
                    #pragma unroll
                    for (int bn = 0; bn < 4; bn++)
                        mma_f16(acc[am][bn], ah2[buf][am], bh2[buf][bn]);
            }

            // prefetch logical double-chunk iter+2 (always commit to keep accounting exact)
            {
                int cl = iter + 2;
                uint32_t stg = dsm + (uint32_t)((sb0 + cl) % NSTAGE) * STAGE_BYTES;
                if (cl < NDC) load_chunk2(stg, i0, j0, cl, tid);
                else if (iter >= 1 && nt < NBLK) load_chunk2(stg, i0n, j0n, cl - NDC, tid);
                CP_COMMIT();
            }
        }

        // ---- fused epilogue ----
        float pm[4], nm[4], cm[8], cnn[8];
        #pragma unroll
        for (int e = 0; e < 4; e++) { pm[e] = 0.f; nm[e] = 3.4e38f; }
        #pragma unroll
        for (int e = 0; e < 8; e++) { cm[e] = 0.f; cnn[e] = 3.4e38f; }

        #pragma unroll
        for (int am = 0; am < 2; am++) {
            #pragma unroll
            for (int h = 0; h < 2; h++) {
                int li = wm * 32 + am * 16 + h * 8 + r_lo;
                int gi = i0 + li;
                int tiv = sti[p][li];
                #pragma unroll
                for (int bn = 0; bn < 4; bn++) {
                    #pragma unroll
                    for (int e2 = 0; e2 < 2; e2++) {
                        int lj = wn * 32 + bn * 8 + c_lo + e2;
                        int gj = j0 + lj;
                        float s = acc[am][bn][h * 2 + e2];
                        float oms = 1.0f - s;
                        float ee = oms * oms;
                        float d2 = fmaxf(2.0f - 2.0f * s, 0.0f);
                        if (diag && gi > gj) continue;
                        if (diag && gi == gj) {
                            posA += ee;
                            if (tiv == 1) semA += ee;
                            continue;
                        }
                        int tjv = stj[p][lj];
                        if (tiv == tjv) {
                            posA += 2.0f * ee;
                            qA += ee;
                            if (tiv == 1) semA += 2.0f * ee;
                            pm[am*2 + h] = fmaxf(pm[am*2 + h], d2);
                            cm[bn*2 + e2] = fmaxf(cm[bn*2 + e2], d2);
                        } else {
                            float cc = fmaxf(s - 0.2f, 0.0f);
                            negA += 2.0f * cc * cc;
                            nm[am*2 + h] = fminf(nm[am*2 + h], d2);
                            cnn[bn*2 + e2] = fminf(cnn[bn*2 + e2], d2);
                        }
                    }
                }
            }
        }

        #pragma unroll
        for (int am = 0; am < 2; am++)
            #pragma unroll
            for (int h = 0; h < 2; h++) {
                int li = wm * 32 + am * 16 + h * 8 + r_lo;
                if (pm[am*2+h] > 0.0f)    atomicMax(&srp[p][li], __float_as_uint(pm[am*2+h]));
                if (nm[am*2+h] < 3.3e38f) atomicMin(&srn[p][li], __float_as_uint(nm[am*2+h]));
            }
        #pragma unroll
        for (int bn = 0; bn < 4; bn++)
            #pragma unroll
            for (int e2 = 0; e2 < 2; e2++) {
                int lj = wn * 32 + bn * 8 + c_lo + e2;
                if (cm[bn*2+e2] > 0.0f)     atomicMax(&scp[p][lj], __float_as_uint(cm[bn*2+e2]));
                if (cnn[bn*2+e2] < 3.3e38f) atomicMin(&scn[p][lj], __float_as_uint(cnn[bn*2+e2]));
            }
        __syncthreads();

        if (tid < 128) {
            if (srp[p][tid] != 0u)          atomicMax(&g_posd2[i0 + tid], srp[p][tid]);
            if (srn[p][tid] != 0x7F7FFFFFu) atomicMin(&g_negd2[i0 + tid], srn[p][tid]);
            if (scp[p][tid] != 0u)          atomicMax(&g_posd2[j0 + tid], scp[p][tid]);
            if (scn[p][tid] != 0x7F7FFFFFu) atomicMin(&g_negd2[j0 + tid], scn[p][tid]);
        }

        if (nt >= NBLK) break;
        tile = nt;
        decode_tile(tile, bi, bj);
        i0 = bi * 128; j0 = bj * 128;
        p ^= 1;
        sb0 = (sb0 + NDC) % NSTAGE;
    }
    CP_WAIT(0);

    // ---- once per CTA: reduce the four sums ----
    float vals4[4] = {posA, negA, semA, qA};
    #pragma unroll
    for (int r = 0; r < 4; r++) {
        float v = vals4[r];
        for (int o = 16; o; o >>= 1) v += __shfl_xor_sync(0xffffffffu, v, o);
        if (lane == 0) sredd[w] = (double)v;
        __syncthreads();
        if (tid == 0) {
            double s = 0.0;
            #pragma unroll
            for (int q = 0; q < 16; q++) s += sredd[q];
            atomicAdd(&g_acc[r], s);
        }
        __syncthreads();
    }

    // ---- last-CTA finalize ----
    __threadfence();
    __shared__ int s_rank;
    if (tid == 0) s_rank = atomicAdd(&g_done, 1);
    __syncthreads();
    if (s_rank != NPERS - 1) return;

    __shared__ double s_sum[5];
    __shared__ int    s_c[CN];
    if (w == 0) {
        double p5[5] = {0,0,0,0,0};
        int    c3[CN] = {0,0,0};
        #pragma unroll
        for (int q = 0; q < 4; q++) {
            int idx = lane + 32 * q;
            #pragma unroll
            for (int r = 0; r < 5; r++) p5[r] += g_rows_part[idx][r];
            #pragma unroll
            for (int r = 0; r < CN; r++) c3[r] += g_cnt_part[idx][r];
        }
        #pragma unroll
        for (int r = 0; r < 5; r++) {
            double v = p5[r];
            for (int o = 16; o; o >>= 1) v += __shfl_xor_sync(0xffffffffu, v, o);
            if (lane == 0) s_sum[r] = v;
        }
        #pragma unroll
        for (int r = 0; r < CN; r++) {
            int v = c3[r];
            for (int o = 16; o; o >>= 1) v += __shfl_xor_sync(0xffffffffu, v, o);
            if (lane == 0) s_c[r] = v;
        }
    }
    __syncthreads();
    int c0 = s_c[0], c1 = s_c[1], c2 = s_c[2];

    __shared__ double sdd[GT];
    __shared__ int    sci[GT];
    double tsum = 0.0; int tcnt = 0;
    for (int i = tid; i < BN; i += GT) {
        int t = targets[i];
        int ct = (t == 0) ? c0 : (t == 1) ? c1 : c2;
        if ((ct >= 2) && ((BN - ct) >= 1)) {
            float hp = sqrtf(__uint_as_float(g_posd2[i]));
            float hn = sqrtf(__uint_as_float(g_negd2[i]));
            float margin = 1.5f * ((t == 1) ? 2.5f : 1.0f);
            float tl = fmaxf(hp - hn + margin, 0.0f);
            tsum += (double)tl;
            tcnt++;
        }
    }
    sdd[tid] = tsum; sci[tid] = tcnt;
    __syncthreads();
    for (int s = GT/2; s; s >>= 1) {
        if (tid < s) { sdd[tid] += sdd[tid + s]; sci[tid] += sci[tid + s]; }
        __syncthreads();
    }
    if (tid == 0) {
        double triplet = (sci[0] > 0) ? sdd[0] / (double)(sci[0] > 1 ? sci[0] : 1) : 0.0;
        double focal = s_sum[0] / (double)BN;
        double wsum = (double)c0*cw[0] + (double)c1*cw[1] + (double)c2*cw[2];
        double ce = s_sum[1] / wsum;
        double boundary = s_sum[2] / ((double)BN + 1e-8);
        double contrastive = (g_acc[0] + g_acc[1] + 4.0*g_acc[2]) / ((double)BN*(double)BN + 1e-8);
        long long sp = (long long)c0*c0 + (long long)c1*c1 + (long long)c2*c2;
        long long npairs = (sp - BN) / 2;
        double q = g_acc[3] / (double)(npairs > 1 ? npairs : 1);
        if (c2 > 0) q *= 1.0 + 2.5 * ((double)c2 / (double)BN);
        double quality = (npairs > 0) ? q : 0.0;
        int epoch = epoch_p[0];
        double ann = (double)epoch / 25.0; ann *= ann; if (ann > 1.0) ann = 1.0;
        double evid = s_sum[3] / (double)BN + ann * 0.2 * (s_sum[4] / (double)BN);
        out[0] = (float)(0.4*focal + 0.3*ce + 0.15*boundary
                       + 0.1*contrastive + 0.1*triplet + 0.1*quality + 0.1*evid);
    }
}

// ---------------- launcher ----------------
extern "C" void kernel_launch(void* const* d_in, const int* in_sizes, int n_in,
                              void* d_out, int out_size) {
    const float* logits   = (const float*)d_in[0];
    const int*   targets  = (const int*)d_in[1];
    const float* features = (const float*)d_in[2];
    const float* alpha    = (const float*)d_in[3];
    const int*   epoch    = (const int*)d_in[4];
    const float* fa       = (const float*)d_in[5];
    const float* cw       = (const float*)d_in[6];
    float* out = (float*)d_out;

    cudaFuncSetAttribute(k_gram, cudaFuncAttributeMaxDynamicSharedMemorySize, DSMEM_BYTES);

    k_prep<<<NPERS, GT>>>(features, logits, targets, alpha, fa, cw);
    k_gram<<<NPERS, GT, DSMEM_BYTES>>>(targets, cw, epoch, out);
}

// round 17
// speedup vs baseline: 1.0566x; 1.0566x over previous
#include <cuda_runtime.h>
#include <cuda_fp16.h>
#include <math.h>
#include <stdint.h>

#define BN 4096
#define DN 512
#define CN 3
#define NTJ 32                      // 128-col blocks
#define NTI 16                      // 256-row blocks
#define NBLK2 272                   // sum_{bi<16} (32-2bi)
#define NCHUNK 8                    // K chunks of 64
#define STAGE_BYTES 49152           // A 32KB + B 16KB
#define NSTAGE 4
#define DSMEM_BYTES (NSTAGE * STAGE_BYTES)
#define NRW 128
#define GT 512
#define NPERS 148

// ---------------- device scratch ----------------
__device__ __align__(16) __half g_hi[BN * DN];
__device__ unsigned int g_posd2[BN];
__device__ unsigned int g_negd2[BN];
__device__ double       g_acc[4];            // 0 pos 1 neg 2 semi 3 q
__device__ double       g_rows_part[NRW][5];
__device__ int          g_cnt_part[NRW][CN];
__device__ int          g_done;
__device__ int          g_work;

// ---------------- PTX helpers (base sm_103-legal only) ----------------
__device__ __forceinline__ uint32_t smem_u32(const void* p) {
    uint32_t a;
    asm("{ .reg .u64 t; cvta.to.shared.u64 t, %1; cvt.u32.u64 %0, t; }" : "=r"(a) : "l"(p));
    return a;
}
#define SW128(x) ((x) ^ (((x) >> 3) & 0x70))

__device__ __forceinline__ void cp16(uint32_t smem, const void* g) {
    asm volatile("cp.async.cg.shared.global [%0], [%1], 16;" :: "r"(smem), "l"(g));
}
#define CP_COMMIT()  asm volatile("cp.async.commit_group;" ::: "memory")
#define CP_WAIT(n)   asm volatile("cp.async.wait_group %0;" :: "n"(n) : "memory")

__device__ __forceinline__ void ldsm_x4(uint32_t& r0, uint32_t& r1, uint32_t& r2, uint32_t& r3,
                                        uint32_t addr) {
    asm volatile("ldmatrix.sync.aligned.m8n8.x4.shared.b16 {%0,%1,%2,%3}, [%4];"
                 : "=r"(r0), "=r"(r1), "=r"(r2), "=r"(r3) : "r"(addr));
}

__device__ __forceinline__ void mma_f16(float* c, const uint32_t* a, const uint32_t* b) {
    asm volatile("mma.sync.aligned.m16n8k16.row.col.f32.f16.f16.f32 "
                 "{%0,%1,%2,%3}, {%4,%5,%6,%7}, {%8,%9}, {%0,%1,%2,%3};"
                 : "+f"(c[0]), "+f"(c[1]), "+f"(c[2]), "+f"(c[3])
                 : "r"(a[0]), "r"(a[1]), "r"(a[2]), "r"(a[3]), "r"(b[0]), "r"(b[1]));
}

// ---------------- misc helpers ----------------
__device__ __forceinline__ float digamma_f(float x) {
    float r = 0.0f;
    while (x < 6.0f) { r -= 1.0f / x; x += 1.0f; }
    float f = 1.0f / (x * x);
    return logf(x) - 0.5f / x
        - f * (1.0f/12.0f - f * (1.0f/120.0f - f * (1.0f/252.0f - f * (1.0f/240.0f))))
        + r;
}

// t -> (bi, bj): bi-th 256-row block, bj-th 128-col block, bj >= 2*bi
__device__ __forceinline__ void decode_tile(int t, int& bi, int& bj) {
    int b = 0, rem = t;
    while (rem >= NTJ - 2 * b) { rem -= NTJ - 2 * b; b++; }
    bi = b;
    bj = 2 * b + rem;
}

// ---------------- prep kernel ----------------
__global__ void __launch_bounds__(GT) k_prep(const float* __restrict__ f, const float* __restrict__ logits,
                       const int* __restrict__ targets, const float* __restrict__ alpha,
                       const float* __restrict__ fa, const float* __restrict__ cw) {
    int tid = threadIdx.x;
    int gid = blockIdx.x * GT + tid;
    int lane = tid & 31;
    int gw = gid >> 5;
    const int TW = NPERS * GT / 32;

    for (int row = gw; row < BN; row += TW) {
        const float4* fr = (const float4*)(f + (size_t)row * DN);
        float4 v[4];
        float ss = 0.0f;
        #pragma unroll
        for (int i = 0; i < 4; i++) {
            v[i] = fr[lane + 32 * i];
            ss += v[i].x*v[i].x + v[i].y*v[i].y + v[i].z*v[i].z + v[i].w*v[i].w;
        }
        for (int o = 16; o; o >>= 1) ss += __shfl_xor_sync(0xffffffffu, ss, o);
        float inv = 1.0f / fmaxf(sqrtf(ss), 1e-12f);
        uint2* out = (uint2*)g_hi + (size_t)row * 128;
        #pragma unroll
        for (int i = 0; i < 4; i++) {
            __half h0 = __float2half_rn(v[i].x * inv), h1 = __float2half_rn(v[i].y * inv);
            __half h2 = __float2half_rn(v[i].z * inv), h3 = __float2half_rn(v[i].w * inv);
            uint2 hv;
            hv.x = (uint32_t)__half_as_ushort(h0) | ((uint32_t)__half_as_ushort(h1) << 16);
            hv.y = (uint32_t)__half_as_ushort(h2) | ((uint32_t)__half_as_ushort(h3) << 16);
            out[lane + 32 * i] = hv;
        }
    }

    if (gid < BN) { g_posd2[gid] = 0u; g_negd2[gid] = 0x7F7FFFFFu; }
    if (gid < 4) g_acc[gid] = 0.0;
    if (gid == 4) g_done = 0;
    if (gid == 5) g_work = 0;

    if (gw < NRW) {
        int i = gw * 32 + lane;
        int t = targets[i];

        float l0 = logits[3*i], l1 = logits[3*i+1], l2 = logits[3*i+2];
        float m  = fmaxf(l0, fmaxf(l1, l2));
        float e0 = expf(l0-m), e1 = expf(l1-m), e2 = expf(l2-m);
        float Z  = e0 + e1 + e2;
        float lse = m + logf(Z);
        float lp0 = l0-lse, lp1 = l1-lse, lp2 = l2-lse;
        float lpt = (t == 0) ? lp0 : (t == 1) ? lp1 : lp2;
        float nll = -lpt;
        float ce_ls = 0.9f * nll - 0.1f * ((lp0+lp1+lp2) * (1.0f/3.0f));
        float pt = expf(-ce_ls);
        float om = 1.0f - pt;
        float fterm = fa[t] * om * om * ce_ls;
        float wnll  = cw[t] * nll;
        float p0 = e0/Z, p1 = e1/Z, p2 = e2/Z;
        float bterm = (t == 0) ? (p1 + 0.6f*p2)
                    : (t == 2) ? (p1 + 0.4f*p0)
                    :            4.5f * (1.0f - p1 + 0.3f*(p0 + p2));

        float a0 = alpha[3*i], a1 = alpha[3*i+1], a2 = alpha[3*i+2];
        float S  = a0 + a1 + a2 + 1e-8f;
        float at = (t == 0) ? a0 : (t == 1) ? a1 : a2;
        float lik = digamma_f(S) - digamma_f(at + 1e-8f);
        float b0 = (t == 0) ? 1.0f : a0;
        float b1 = (t == 1) ? 1.0f : a1;
        float b2 = (t == 2) ? 1.0f : a2;
        float ats = b0 + b1 + b2 + 1e-8f;
        float dga = digamma_f(ats + 1e-8f);
        float kl = lgammaf(ats) - (lgammaf(b0+1e-8f) + lgammaf(b1+1e-8f) + lgammaf(b2+1e-8f))
                 + (b0-1.0f) * (digamma_f(b0+1e-8f) - dga)
                 + (b1-1.0f) * (digamma_f(b1+1e-8f) - dga)
                 + (b2-1.0f) * (digamma_f(b2+1e-8f) - dga);

        double vals[5] = { (double)fterm, (double)wnll, (double)bterm, (double)lik, (double)kl };
        #pragma unroll
        for (int r = 0; r < 5; r++) {
            double v = vals[r];
            for (int o = 16; o; o >>= 1) v += __shfl_xor_sync(0xffffffffu, v, o);
            if (lane == 0) g_rows_part[gw][r] = v;
        }
        #pragma unroll
        for (int r = 0; r < CN; r++) {
            int v = (t == r) ? 1 : 0;
            for (int o = 16; o; o >>= 1) v += __shfl_xor_sync(0xffffffffu, v, o);
            if (lane == 0) g_cnt_part[gw][r] = v;
        }
    }
}

// gmem -> smem loader: A 256 rows (32KB) + B 128 rows (16KB), chunk c of K=64
__device__ __forceinline__ void load_chunk(uint32_t sb, int i0, int j0, int c, int tid) {
    const uint4* gh4 = (const uint4*)g_hi;
    #pragma unroll
    for (int p = 0; p < 4; p++) {
        int lin = p * GT + tid;
        int r = lin >> 3, q = lin & 7;
        uint32_t so = SW128((uint32_t)(r * 128 + q * 16));
        cp16(sb + so, gh4 + (size_t)(i0 + r) * 64 + c * 8 + q);
    }
    #pragma unroll
    for (int p = 0; p < 2; p++) {
        int lin = p * GT + tid;
        int r = lin >> 3, q = lin & 7;
        uint32_t so = SW128((uint32_t)(r * 128 + q * 16));
        cp16(sb + 32768 + so, gh4 + (size_t)(j0 + r) * 64 + c * 8 + q);
    }
}

// persistent HMMA Gram kernel: 256x128 CTA tiles, 64x32 warp tiles, rolling 4-stage pipeline
__global__ void __launch_bounds__(GT, 1) k_gram(const int* __restrict__ targets,
                                                const float* __restrict__ cw,
                                                const int* __restrict__ epoch_p,
                                                float* __restrict__ out) {
    extern __shared__ __align__(1024) char dsm_raw[];
    __shared__ int sti[2][256], stj[2][128];
    __shared__ unsigned int srp[2][256], srn[2][256], scp[2][128], scn[2][128];
    __shared__ double sredd[16];
    __shared__ int s_cur, s_next;

    int tid = threadIdx.x;
    int w = tid >> 5, lane = tid & 31;
    int wm = w >> 2, wn = w & 3;     // 4x4 warp grid -> 64x32 region per warp
    uint32_t dsm = smem_u32(dsm_raw);

    int a_row = wm * 64 + (lane & 15);
    int a_colb = (lane >> 4) * 8;
    int b_row = wn * 32 + (lane & 7) + ((lane >> 4) << 3);
    int b_colb = ((lane >> 3) & 1) * 8;
    int r_lo = lane >> 2;
    int c_lo = (lane & 3) * 2;

    float posA = 0.f, negA = 0.f, semA = 0.f, qA = 0.f;

    if (tid == 0) s_cur = atomicAdd(&g_work, 1);
    __syncthreads();
    int tile = s_cur;                // < NPERS <= NBLK2, always valid
    int bi, bj;
    decode_tile(tile, bi, bj);
    int i0 = bi * 256, j0 = bj * 128;
    int p = 0;
    if (tid < 256) {
        sti[0][tid] = targets[i0 + tid];
        srp[0][tid] = 0u; srn[0][tid] = 0x7F7FFFFFu;
    }
    if (tid < 128) {
        stj[0][tid] = targets[j0 + tid];
        scp[0][tid] = 0u; scn[0][tid] = 0x7F7FFFFFu;
    }
    int sb0 = 0;   // stage of this tile's chunk 0 (realigns mod 4 every tile: 8%4==0)
    #pragma unroll
    for (int c = 0; c < 3; c++) {
        load_chunk(dsm + (uint32_t)((sb0 + c) % NSTAGE) * STAGE_BYTES, i0, j0, c, tid);
        CP_COMMIT();
    }

    for (;;) {
        int i0n = 0, j0n = 0, nt = NBLK2;

        float acc[4][4][4];
        #pragma unroll
        for (int am = 0; am < 4; am++)
            #pragma unroll
            for (int bn = 0; bn < 4; bn++)
                #pragma unroll
                for (int e = 0; e < 4; e++) acc[am][bn][e] = 0.0f;

        #pragma unroll
        for (int iter = 0; iter < NCHUNK; iter++) {
            CP_WAIT(2);
            __syncthreads();
            if (iter == 0 && tid == 0) s_next = atomicAdd(&g_work, 1);
            if (iter == 1) {
                nt = s_next;
                if (nt < NBLK2) {
                    int bin, bjn;
                    decode_tile(nt, bin, bjn);
                    i0n = bin * 256; j0n = bjn * 128;
                }
                if (tid < 256) {
                    if (nt < NBLK2) sti[p ^ 1][tid] = targets[i0n + tid];
                    srp[p ^ 1][tid] = 0u; srn[p ^ 1][tid] = 0x7F7FFFFFu;
                }
                if (tid < 128) {
                    if (nt < NBLK2) stj[p ^ 1][tid] = targets[j0n + tid];
                    scp[p ^ 1][tid] = 0u; scn[p ^ 1][tid] = 0x7F7FFFFFu;
                }
            }

            uint32_t sb = dsm + (uint32_t)((sb0 + iter) % NSTAGE) * STAGE_BYTES;
            #pragma unroll
            for (int ks = 0; ks < 4; ks++) {
                int k0 = ks * 16;
                uint32_t ah[4][4], bh[4][2];
                #pragma unroll
                for (int am = 0; am < 4; am++) {
                    uint32_t off = SW128((uint32_t)((a_row + am * 16) * 128 + (k0 + a_colb) * 2));
                    ldsm_x4(ah[am][0], ah[am][1], ah[am][2], ah[am][3], sb + off);
                }
                #pragma unroll
                for (int bp = 0; bp < 2; bp++) {
                    uint32_t off = SW128((uint32_t)((b_row + bp * 16) * 128 + (k0 + b_colb) * 2));
                    ldsm_x4(bh[bp*2][0], bh[bp*2][1], bh[bp*2+1][0], bh[bp*2+1][1], sb + 32768 + off);
                }
                #pragma unroll
                for (int am = 0; am < 4; am++)
                    #pragma unroll
                    for (int bn = 0; bn < 4; bn++)
                        mma_f16(acc[am][bn], ah[am], bh[bn]);
            }

            // prefetch logical chunk iter+3 (always commit for exact accounting)
            {
                int cl = iter + 3;
                uint32_t stg = dsm + (uint32_t)((sb0 + cl) % NSTAGE) * STAGE_BYTES;
                if (cl < NCHUNK) load_chunk(stg, i0, j0, cl, tid);
                else if (iter >= 1 && nt < NBLK2) load_chunk(stg, i0n, j0n, cl - NCHUNK, tid);
                CP_COMMIT();
            }
        }

        // ---- fused epilogue (uniform gi vs gj rules handle diag/lower) ----
        float pm[8], nm[8], cm[8], cnn[8];
        #pragma unroll
        for (int e = 0; e < 8; e++) { pm[e] = 0.f; nm[e] = 3.4e38f; cm[e] = 0.f; cnn[e] = 3.4e38f; }

        #pragma unroll
        for (int am = 0; am < 4; am++) {
            #pragma unroll
            for (int h = 0; h < 2; h++) {
                int li = wm * 64 + am * 16 + h * 8 + r_lo;
                int gi = i0 + li;
                int tiv = sti[p][li];
                #pragma unroll
                for (int bn = 0; bn < 4; bn++) {
                    #pragma unroll
                    for (int e2 = 0; e2 < 2; e2++) {
                        int lj = wn * 32 + bn * 8 + c_lo + e2;
                        int gj = j0 + lj;
                        if (gi > gj) continue;
                        float s = acc[am][bn][h * 2 + e2];
                        float oms = 1.0f - s;
                        float ee = oms * oms;
                        float d2 = fmaxf(2.0f - 2.0f * s, 0.0f);
                        if (gi == gj) {
                            posA += ee;
                            if (tiv == 1) semA += ee;
                            continue;
                        }
                        int tjv = stj[p][lj];
                        int ri = am * 2 + h, cj = bn * 2 + e2;
                        if (tiv == tjv) {
                            posA += 2.0f * ee;
                            qA += ee;
                            if (tiv == 1) semA += 2.0f * ee;
                            pm[ri] = fmaxf(pm[ri], d2);
                            cm[cj] = fmaxf(cm[cj], d2);
                        } else {
                            float cc = fmaxf(s - 0.2f, 0.0f);
                            negA += 2.0f * cc * cc;
                            nm[ri] = fminf(nm[ri], d2);
                            cnn[cj] = fminf(cnn[cj], d2);
                        }
                    }
                }
            }
        }

        #pragma unroll
        for (int am = 0; am < 4; am++)
            #pragma unroll
            for (int h = 0; h < 2; h++) {
                int li = wm * 64 + am * 16 + h * 8 + r_lo;
                int ri = am * 2 + h;
                if (pm[ri] > 0.0f)    atomicMax(&srp[p][li], __float_as_uint(pm[ri]));
                if (nm[ri] < 3.3e38f) atomicMin(&srn[p][li], __float_as_uint(nm[ri]));
            }
        #pragma unroll
        for (int bn = 0; bn < 4; bn++)
            #pragma unroll
            for (int e2 = 0; e2 < 2; e2++) {
                int lj = wn * 32 + bn * 8 + c_lo + e2;
                int cj = bn * 2 + e2;
                if (cm[cj] > 0.0f)     atomicMax(&scp[p][lj], __float_as_uint(cm[cj]));
                if (cnn[cj] < 3.3e38f) atomicMin(&scn[p][lj], __float_as_uint(cnn[cj]));
            }
        __syncthreads();

        if (tid < 256) {
            if (srp[p][tid] != 0u)          atomicMax(&g_posd2[i0 + tid], srp[p][tid]);
            if (srn[p][tid] != 0x7F7FFFFFu) atomicMin(&g_negd2[i0 + tid], srn[p][tid]);
        }
        if (tid < 128) {
            if (scp[p][tid] != 0u)          atomicMax(&g_posd2[j0 + tid], scp[p][tid]);
            if (scn[p][tid] != 0x7F7FFFFFu) atomicMin(&g_negd2[j0 + tid], scn[p][tid]);
        }

        if (nt >= NBLK2) break;
        tile = nt;
        decode_tile(tile, bi, bj);
        i0 = bi * 256; j0 = bj * 128;
        p ^= 1;
        // sb0 = (sb0 + 8) % 4 == sb0  (stages realign every tile)
    }
    CP_WAIT(0);

    // ---- once per CTA: reduce the four sums (shuffle + 16-entry pass) ----
    float vals4[4] = {posA, negA, semA, qA};
    #pragma unroll
    for (int r = 0; r < 4; r++) {
        float v = vals4[r];
        for (int o = 16; o; o >>= 1) v += __shfl_xor_sync(0xffffffffu, v, o);
        if (lane == 0) sredd[w] = (double)v;
        __syncthreads();
        if (tid == 0) {
            double s = 0.0;
            #pragma unroll
            for (int q = 0; q < 16; q++) s += sredd[q];
            atomicAdd(&g_acc[r], s);
        }
        __syncthreads();
    }

    // ---- last-CTA finalize ----
    __threadfence();
    __shared__ int s_rank;
    if (tid == 0) s_rank = atomicAdd(&g_done, 1);
    __syncthreads();
    if (s_rank != NPERS - 1) return;

    __shared__ double s_sum[5];
    __shared__ int    s_c[CN];
    if (w == 0) {
        double p5[5] = {0,0,0,0,0};
        int    c3[CN] = {0,0,0};
        #pragma unroll
        for (int q = 0; q < 4; q++) {
            int idx = lane + 32 * q;
            #pragma unroll
            for (int r = 0; r < 5; r++) p5[r] += g_rows_part[idx][r];
            #pragma unroll
            for (int r = 0; r < CN; r++) c3[r] += g_cnt_part[idx][r];
        }
        #pragma unroll
        for (int r = 0; r < 5; r++) {
            double v = p5[r];
            for (int o = 16; o; o >>= 1) v += __shfl_xor_sync(0xffffffffu, v, o);
            if (lane == 0) s_sum[r] = v;
        }
        #pragma unroll
        for (int r = 0; r < CN; r++) {
            int v = c3[r];
            for (int o = 16; o; o >>= 1) v += __shfl_xor_sync(0xffffffffu, v, o);
            if (lane == 0) s_c[r] = v;
        }
    }
    __syncthreads();
    int c0 = s_c[0], c1 = s_c[1], c2 = s_c[2];

    __shared__ double sdd[GT];
    __shared__ int    sci[GT];
    double tsum = 0.0; int tcnt = 0;
    for (int i = tid; i < BN; i += GT) {
        int t = targets[i];
        int ct = (t == 0) ? c0 : (t == 1) ? c1 : c2;
        if ((ct >= 2) && ((BN - ct) >= 1)) {
            float hp = sqrtf(__uint_as_float(g_posd2[i]));
            float hn = sqrtf(__uint_as_float(g_negd2[i]));
            float margin = 1.5f * ((t == 1) ? 2.5f : 1.0f);
            float tl = fmaxf(hp - hn + margin, 0.0f);
            tsum += (double)tl;
            tcnt++;
        }
    }
    sdd[tid] = tsum; sci[tid] = tcnt;
    __syncthreads();
    for (int s = GT/2; s; s >>= 1) {
        if (tid < s) { sdd[tid] += sdd[tid + s]; sci[tid] += sci[tid + s]; }
        __syncthreads();
    }
    if (tid == 0) {
        double triplet = (sci[0] > 0) ? sdd[0] / (double)(sci[0] > 1 ? sci[0] : 1) : 0.0;
        double focal = s_sum[0] / (double)BN;
        double wsum = (double)c0*cw[0] + (double)c1*cw[1] + (double)c2*cw[2];
        double ce = s_sum[1] / wsum;
        double boundary = s_sum[2] / ((double)BN + 1e-8);
        double contrastive = (g_acc[0] + g_acc[1] + 4.0*g_acc[2]) / ((double)BN*(double)BN + 1e-8);
        long long sp = (long long)c0*c0 + (long long)c1*c1 + (long long)c2*c2;
        long long npairs = (sp - BN) / 2;
        double q = g_acc[3] / (double)(npairs > 1 ? npairs : 1);
        if (c2 > 0) q *= 1.0 + 2.5 * ((double)c2 / (double)BN);
        double quality = (npairs > 0) ? q : 0.0;
        int epoch = epoch_p[0];
        double ann = (double)epoch / 25.0; ann *= ann; if (ann > 1.0) ann = 1.0;
        double evid = s_sum[3] / (double)BN + ann * 0.2 * (s_sum[4] / (double)BN);
        out[0] = (float)(0.4*focal + 0.3*ce + 0.15*boundary
                       + 0.1*contrastive + 0.1*triplet + 0.1*quality + 0.1*evid);
    }
}

// ---------------- launcher ----------------
extern "C" void kernel_launch(void* const* d_in, const int* in_sizes, int n_in,
                              void* d_out, int out_size) {
    const float* logits   = (const float*)d_in[0];
    const int*   targets  = (const int*)d_in[1];
    const float* features = (const float*)d_in[2];
    const float* alpha    = (const float*)d_in[3];
    const int*   epoch    = (const int*)d_in[4];
    const float* fa       = (const float*)d_in[5];
    const float* cw       = (const float*)d_in[6];
    float* out = (float*)d_out;

    cudaFuncSetAttribute(k_gram, cudaFuncAttributeMaxDynamicSharedMemorySize, DSMEM_BYTES);

    k_prep<<<NPERS, GT>>>(features, logits, targets, alpha, fa, cw);
    k_gram<<<NPERS, GT, DSMEM_BYTES>>>(targets, cw, epoch, out);
}